// round 6
// baseline (speedup 1.0000x reference)
#include <cuda_runtime.h>

// out[i,c] = 8! * sum_j ( relu(x @ W1 + b1) @ W2 + b2 )[j,c]   (row-constant)
//
// R6 vs R5:
//  - first full-CTA barrier -> __syncwarp (x transpose is warp-local)
//  - mainloop 8 instr/iter: rows (0,1)(2,3)(4,5)(6,7)(8,pad) as 5 packed
//    f32x2 accumulators; W1 pairs pre-packed during the LDG shadow
//  - final sync is a named barrier over warps 0..8 only; warps 9..15 exit

static constexpr int N = 9;
static constexpr int D = 512;
static constexpr int H = 32;
static constexpr int THREADS = 512;
static constexpr int WARPS = 16;
static constexpr int DPW = D / WARPS;     // 32 d-values per warp
static constexpr int XPAD = 12;           // floats per xT row (48B)
static constexpr float FACT8 = 40320.0f;  // (N-1)!

__global__ void __launch_bounds__(THREADS, 1)
sym_kernel(const float* __restrict__ x,
           const float* __restrict__ W1,
           const float* __restrict__ b1,
           const float* __restrict__ W2,
           const float* __restrict__ b2,
           float* __restrict__ out) {
    __shared__ __align__(16) float xT[D * XPAD];        // xT[d][r]
    __shared__ __align__(16) float psum[WARPS * N * H]; // [w][r*H + k]
    __shared__ __align__(16) float h[N * H];

    const int t = threadIdx.x;
    const int w = t >> 5;   // warp 0..15
    const int k = t & 31;   // lane / hidden unit

    // ---- per-warp prefetch (no CTA-wide barrier needed) ----
    // x transpose: thread t owns column d=t (9 coalesced scalar LDGs,
    // STS lane stride = XPAD -> <=4-way).
#pragma unroll
    for (int r = 0; r < N; r++)
        xT[t * XPAD + r] = x[r * D + t];

    // W1 chunk -> packed (wv,wv) 64-bit registers, packing in the LDG shadow
    unsigned long long wpack[DPW];
    const float* W1p = W1 + (w * DPW) * H + k;
#pragma unroll
    for (int i = 0; i < DPW; i++) {
        unsigned int wu = __float_as_uint(W1p[i * H]);
        asm("mov.b64 %0, {%1, %1};" : "=l"(wpack[i]) : "r"(wu));
    }

    const float b1r = b1[k];

    // tail operands live only in warp 0
    float4 w2r = make_float4(0.f, 0.f, 0.f, 0.f);
    float  b2r = 0.f;
    if (w == 0) {
        w2r = *(const float4*)(W2 + k * 4);
        if (k < 4) b2r = b2[k];
    }
    __syncwarp();   // xT slice is written/read by this warp only

    // ---- rank-1-update partial dots: 5 packed accumulators ----
    // (0,1)(2,3)(4,5)(6,7)(8,pad) -- pad half discarded.
    unsigned long long a01 = 0, a23 = 0, a45 = 0, a67 = 0, a89 = 0;
    const float* xrow = xT + (w * DPW) * XPAD;
#pragma unroll
    for (int i = 0; i < DPW; i++) {
        const float* xp = xrow + i * XPAD;               // 48B-aligned
        ulonglong2 p0 = *(const ulonglong2*)(xp);        // rows 0..3 (bcast)
        unsigned long long p2 = *(const unsigned long long*)(xp + 4);  // 4,5
        unsigned long long p3 = *(const unsigned long long*)(xp + 6);  // 6,7
        unsigned long long p4 = *(const unsigned long long*)(xp + 8);  // 8,pad
        unsigned long long ww = wpack[i];
        asm("fma.rn.f32x2 %0, %1, %2, %0;" : "+l"(a01) : "l"(p0.x), "l"(ww));
        asm("fma.rn.f32x2 %0, %1, %2, %0;" : "+l"(a23) : "l"(p0.y), "l"(ww));
        asm("fma.rn.f32x2 %0, %1, %2, %0;" : "+l"(a45) : "l"(p2),   "l"(ww));
        asm("fma.rn.f32x2 %0, %1, %2, %0;" : "+l"(a67) : "l"(p3),   "l"(ww));
        asm("fma.rn.f32x2 %0, %1, %2, %0;" : "+l"(a89) : "l"(p4),   "l"(ww));
    }
    {
        float ar[9];
        unsigned int u0, u1;
        asm("mov.b64 {%0, %1}, %2;" : "=r"(u0), "=r"(u1) : "l"(a01));
        ar[0] = __uint_as_float(u0); ar[1] = __uint_as_float(u1);
        asm("mov.b64 {%0, %1}, %2;" : "=r"(u0), "=r"(u1) : "l"(a23));
        ar[2] = __uint_as_float(u0); ar[3] = __uint_as_float(u1);
        asm("mov.b64 {%0, %1}, %2;" : "=r"(u0), "=r"(u1) : "l"(a45));
        ar[4] = __uint_as_float(u0); ar[5] = __uint_as_float(u1);
        asm("mov.b64 {%0, %1}, %2;" : "=r"(u0), "=r"(u1) : "l"(a67));
        ar[6] = __uint_as_float(u0); ar[7] = __uint_as_float(u1);
        asm("mov.b64 {%0, %1}, %2;" : "=r"(u0), "=r"(u1) : "l"(a89));
        ar[8] = __uint_as_float(u0);   // low half only; pad discarded
        float* pp = psum + w * (N * H) + k;   // lane stride 1: conflict-free
#pragma unroll
        for (int r = 0; r < N; r++) pp[r * H] = ar[r];
    }
    __syncthreads();   // psum crosses all 16 warps

    // warps 9..15 are done
    if (w >= 9) return;

    // ---- reduce the 16 warp partials (fixed order), bias, relu ----
    if (t < N * H) {
        float q[WARPS];
#pragma unroll
        for (int j = 0; j < WARPS; j++)
            q[j] = psum[j * (N * H) + t];   // consecutive-per-thread: CF
        float sum = (((q[0] + q[1]) + (q[2] + q[3])) + ((q[4] + q[5]) + (q[6] + q[7])))
                  + (((q[8] + q[9]) + (q[10] + q[11])) + ((q[12] + q[13]) + (q[14] + q[15])));
        h[t] = fmaxf(sum + b1r, 0.0f);
    }
    asm volatile("bar.sync 1, %0;" :: "r"(N * H) : "memory");  // warps 0..8 only

    // ---- warp 0 finishes with shuffles (fixed tree, deterministic) ----
    if (w == 0) {
        float s = 0.f;
#pragma unroll
        for (int r = 0; r < N; r++) s += h[r * H + k];   // CF (stride 32)

        float v0 = s * w2r.x, v1 = s * w2r.y, v2 = s * w2r.z, v3 = s * w2r.w;
#pragma unroll
        for (int off = 16; off; off >>= 1) {
            v0 += __shfl_xor_sync(0xffffffffu, v0, off);
            v1 += __shfl_xor_sync(0xffffffffu, v1, off);
            v2 += __shfl_xor_sync(0xffffffffu, v2, off);
            v3 += __shfl_xor_sync(0xffffffffu, v3, off);
        }

        const int c = k & 3;
        float b2c  = __shfl_sync(0xffffffffu, b2r, c);
        float vsel = (c == 0) ? v0 : (c == 1) ? v1 : (c == 2) ? v2 : v3;
        float val  = FACT8 * fmaf((float)N, b2c, vsel);

        out[k] = val;                   // positions 0..31
        if (k < 4) out[32 + k] = val;   // positions 32..35
    }
}

extern "C" void kernel_launch(void* const* d_in, const int* in_sizes, int n_in,
                              void* d_out, int out_size) {
    // metadata order: x[9,512], W1[512,32], b1[32], W2[32,4], b2[4], perms (unused)
    const float* x  = (const float*)d_in[0];
    const float* W1 = (const float*)d_in[1];
    const float* b1 = (const float*)d_in[2];
    const float* W2 = (const float*)d_in[3];
    const float* b2 = (const float*)d_in[4];
    float* out = (float*)d_out;

    sym_kernel<<<1, THREADS>>>(x, W1, b1, W2, b2, out);
}

// round 7
// speedup vs baseline: 1.3835x; 1.3835x over previous
#include <cuda_runtime.h>

// out[i,c] = 8! * sum_j ( relu(x @ W1 + b1) @ W2 + b2 )[j,c]   (row-constant)
//
// R7 vs R6:
//  - psum stored as packed f32x2 pairs (5x STS.64, no unpacking of the
//    packed accumulators); cross-warp reduce uses add.rn.f32x2 on pairs
//    (160 threads instead of 288).
//  - warps 5..15: bar.arrive + exit after producing psum; warps 0..4 bar.sync.
//  - tail split across warps 0..3 (one output column each, one butterfly
//    chain per warp); lanes 0..8 store out[r*4+c] directly.

static constexpr int N = 9;
static constexpr int D = 512;
static constexpr int H = 32;
static constexpr int THREADS = 512;
static constexpr int WARPS = 16;
static constexpr int DPW = D / WARPS;     // 32 d-values per warp
static constexpr int XPAD = 12;           // floats per xT row (48B, 16B-mult)
static constexpr int PAIRS = 5;           // row pairs (0,1)(2,3)(4,5)(6,7)(8,pad)
static constexpr float FACT8 = 40320.0f;  // (N-1)!

__global__ void __launch_bounds__(THREADS, 1)
sym_kernel(const float* __restrict__ x,
           const float* __restrict__ W1,
           const float* __restrict__ b1,
           const float* __restrict__ W2,
           const float* __restrict__ b2,
           float* __restrict__ out) {
    __shared__ __align__(16) float xT[D * XPAD];                    // xT[d][r]
    __shared__ __align__(16) unsigned long long psum[WARPS * PAIRS * H]; // [w][p*H+k]
    __shared__ __align__(16) float h[N * H];                        // h[r][k]

    const int t = threadIdx.x;
    const int w = t >> 5;   // warp 0..15
    const int k = t & 31;   // lane

    // ---- per-warp prefetch (no CTA barrier before mainloop) ----
    // x transpose: thread t owns column d=t; 9 coalesced scalar LDGs.
#pragma unroll
    for (int r = 0; r < N; r++)
        xT[t * XPAD + r] = x[r * D + t];
    xT[t * XPAD + 9] = 0.0f;   // pad slot read by the packed row-8 accumulator

    // W1 chunk -> packed (wv,wv) 64-bit registers (packing in LDG shadow)
    unsigned long long wpack[DPW];
    const float* W1p = W1 + (w * DPW) * H + k;
#pragma unroll
    for (int i = 0; i < DPW; i++) {
        unsigned int wu = __float_as_uint(W1p[i * H]);
        asm("mov.b64 %0, {%1, %1};" : "=l"(wpack[i]) : "r"(wu));
    }

    // phase-specific operands
    float b1r = 0.f;
    if (w < PAIRS) b1r = b1[k];              // reduce phase (warps 0..4)
    float w2c = 0.f, b2c = 0.f;
    if (w < 4) {                             // tail: warp c owns column c
        w2c = W2[k * 4 + w];                 // W2[k][c]
        b2c = b2[w];
    }
    __syncwarp();   // xT slice is produced and consumed by this warp only

    // ---- rank-1-update partial dots: 5 packed f32x2 accumulators ----
    unsigned long long a01 = 0, a23 = 0, a45 = 0, a67 = 0, a89 = 0;
    const float* xrow = xT + (w * DPW) * XPAD;
#pragma unroll
    for (int i = 0; i < DPW; i++) {
        const float* xp = xrow + i * XPAD;                  // 48B-aligned
        ulonglong2 p0 = *(const ulonglong2*)(xp);           // rows 0..3
        unsigned long long p2 = *(const unsigned long long*)(xp + 4);  // 4,5
        unsigned long long p3 = *(const unsigned long long*)(xp + 6);  // 6,7
        unsigned long long p4 = *(const unsigned long long*)(xp + 8);  // 8,pad
        unsigned long long ww = wpack[i];
        asm("fma.rn.f32x2 %0, %1, %2, %0;" : "+l"(a01) : "l"(p0.x), "l"(ww));
        asm("fma.rn.f32x2 %0, %1, %2, %0;" : "+l"(a23) : "l"(p0.y), "l"(ww));
        asm("fma.rn.f32x2 %0, %1, %2, %0;" : "+l"(a45) : "l"(p2),   "l"(ww));
        asm("fma.rn.f32x2 %0, %1, %2, %0;" : "+l"(a67) : "l"(p3),   "l"(ww));
        asm("fma.rn.f32x2 %0, %1, %2, %0;" : "+l"(a89) : "l"(p4),   "l"(ww));
    }
    // packed stores, lane stride 1 (conflict-free STS.64)
    {
        unsigned long long* pp = psum + w * (PAIRS * H) + k;
        pp[0 * H] = a01;
        pp[1 * H] = a23;
        pp[2 * H] = a45;
        pp[3 * H] = a67;
        pp[4 * H] = a89;
    }

    // producers (warps 5..15) signal and exit; consumers (0..4) wait
    if (w >= PAIRS) {
        asm volatile("bar.arrive 0, %0;" :: "r"(THREADS) : "memory");
        return;
    }
    asm volatile("bar.sync 0, %0;" :: "r"(THREADS) : "memory");

    // ---- reduce 16 warp partials per (pair, k) slot: packed adds ----
    {
        // warp p (0..4) handles row pair p, lane k
        unsigned long long q[WARPS];
#pragma unroll
        for (int j = 0; j < WARPS; j++)
            q[j] = psum[j * (PAIRS * H) + w * H + k];   // LDS.64, CF
#pragma unroll
        for (int st = 1; st < WARPS; st <<= 1)          // fixed tree
#pragma unroll
            for (int j = 0; j < WARPS; j += 2 * st)
                asm("add.rn.f32x2 %0, %0, %1;" : "+l"(q[j]) : "l"(q[j + st]));
        unsigned int lo, hi;
        asm("mov.b64 {%0, %1}, %2;" : "=r"(lo), "=r"(hi) : "l"(q[0]));
        float hl = fmaxf(__uint_as_float(lo) + b1r, 0.0f);
        h[(2 * w) * H + k] = hl;                         // STS lane stride 1
        if (w < 4) {
            float hh = fmaxf(__uint_as_float(hi) + b1r, 0.0f);
            h[(2 * w + 1) * H + k] = hh;
        }
    }
    asm volatile("bar.sync 1, %0;" :: "r"(PAIRS * H) : "memory");  // warps 0..4
    if (w == 4) return;

    // ---- tail: warp c computes output column c ----
    {
        float s = 0.f;
#pragma unroll
        for (int r = 0; r < N; r++) s += h[r * H + k];   // CF (stride 32)

        float v = s * w2c;                               // v_c partial, lane k
#pragma unroll
        for (int off = 16; off; off >>= 1)               // fixed xor tree
            v += __shfl_xor_sync(0xffffffffu, v, off);

        float val = FACT8 * fmaf((float)N, b2c, v);
        if (k < N) out[k * 4 + w] = val;                 // out[r][c], r=lane
    }
}

extern "C" void kernel_launch(void* const* d_in, const int* in_sizes, int n_in,
                              void* d_out, int out_size) {
    // metadata order: x[9,512], W1[512,32], b1[32], W2[32,4], b2[4], perms (unused)
    const float* x  = (const float*)d_in[0];
    const float* W1 = (const float*)d_in[1];
    const float* b1 = (const float*)d_in[2];
    const float* W2 = (const float*)d_in[3];
    const float* b2 = (const float*)d_in[4];
    float* out = (float*)d_out;

    sym_kernel<<<1, THREADS>>>(x, W1, b1, W2, b2, out);
}